// round 14
// baseline (speedup 1.0000x reference)
#include <cuda_runtime.h>
#include <cuda_fp16.h>
#include <cstdint>

#define N_TOT   8192
#define D_DIM   256
#define TILE_M  128
#define B_HALF  4096
#define NROWT   64
#define K_STEPS 16
#define NTILES  2080
#define NCTA    148
#define ROWS_PER_CTA 56            // 148*56 = 8288 >= 8192

#define ROW_BYTES 528
#define A_OFF   0
#define B0_OFF  (TILE_M * ROW_BYTES)
#define B1_OFF  (B0_OFF + TILE_M * ROW_BYTES)
#define RED_OFF (B1_OFF + TILE_M * ROW_BYTES)
#define SMEM_TOTAL (RED_OFF + 128 * 4 * 2 * 4)

// -------- device scratch --------
__device__ __align__(16) __half g_h[N_TOT * D_DIM];
__device__ int   lab_buf[N_TOT];

#define PR_ALL  0
#define PR_POS  (8 * N_TOT)
#define PC_ALL  (16 * N_TOT)
#define PC_POS  (PC_ALL + 128 * N_TOT)
#define SCRATCH_FLOATS (PC_POS + 128 * N_TOT)
__device__ __align__(16) float scratch[SCRATCH_FLOATS];
__device__ float blocksum[NCTA];

// grid-sync state (counters self-reset via wrap; flag reset by last CTA)
__device__ unsigned g_cnt2 = 0, g_cnt3 = 0;
__device__ volatile int g_flag2 = 0;

// ======================= helpers =======================
static __device__ __forceinline__ uint32_t smem_u32(const void* p) {
    uint32_t a;
    asm("{ .reg .u64 t; cvta.to.shared.u64 t, %1; cvt.u32.u64 %0, t; }" : "=r"(a) : "l"(p));
    return a;
}
static __device__ __forceinline__ float ex2f(float x) {
    float r; asm("ex2.approx.ftz.f32 %0, %1;" : "=f"(r) : "f"(x)); return r;
}
static __device__ __forceinline__ uint32_t pack_h2(float lo, float hi) {
    uint32_t r; asm("cvt.rn.f16x2.f32 %0, %1, %2;" : "=r"(r) : "f"(hi), "f"(lo)); return r;
}
static __device__ __forceinline__ void cp16(uint32_t saddr, const void* g) {
    asm volatile("cp.async.cg.shared.global [%0], [%1], 16;" :: "r"(saddr), "l"(g) : "memory");
}
#define CP_COMMIT() asm volatile("cp.async.commit_group;" ::: "memory")
#define CP_WAIT(n)  asm volatile("cp.async.wait_group %0;" :: "n"(n) : "memory")

static __device__ __forceinline__ void ldsm_x4(uint32_t& r0, uint32_t& r1,
                                               uint32_t& r2, uint32_t& r3, uint32_t a) {
    asm volatile("ldmatrix.sync.aligned.m8n8.x4.shared.b16 {%0,%1,%2,%3}, [%4];"
                 : "=r"(r0), "=r"(r1), "=r"(r2), "=r"(r3) : "r"(a));
}
static __device__ __forceinline__ void mma16816_f16(uint32_t* d, const uint32_t* a,
                                                    uint32_t b0, uint32_t b1) {
    asm volatile(
        "mma.sync.aligned.m16n8k16.row.col.f16.f16.f16.f16 "
        "{%0,%1}, {%2,%3,%4,%5}, {%6,%7}, {%0,%1};"
        : "+r"(d[0]), "+r"(d[1])
        : "r"(a[0]), "r"(a[1]), "r"(a[2]), "r"(a[3]), "r"(b0), "r"(b1));
}

// full grid barrier: 1 CTA/SM -> all co-resident -> spin is safe
static __device__ __forceinline__ void grid_bar(unsigned* cnt, volatile int* flag) {
    __syncthreads();
    if (threadIdx.x == 0) {
        __threadfence();
        unsigned t = atomicInc(cnt, NCTA - 1);      // wraps to 0 -> self-resets
        if (t == NCTA - 1) { *flag = 1; }
        else { while (*flag == 0) { __nanosleep(64); } }
        __threadfence();
    }
    __syncthreads();
}

// ---- schedule mapping (pair order: [64][1][63][2]...[33][32]) ----
static __device__ __forceinline__ void map_u(int u, int& it, int& jt) {
    int p = u / 65, off = u - p * 65;
    int l0 = 64 - p;
    if (off < l0) { it = p;      jt = p + off; }
    else          { it = 63 - p; jt = (63 - p) + (off - l0); }
}
static __device__ __forceinline__ int map_jt(int u) {
    int it, jt; map_u(u, it, jt); return jt;
}
static __device__ __forceinline__ int chunk_of(int u) {
    return (u < 120) ? (u / 15) : (8 + (u - 120) / 14);
}
static __device__ __forceinline__ int strip_start(int it) {
    int p = (it < 32) ? it : 63 - it;
    return (it < 32) ? (65 * p) : (65 * p + (64 - p));
}
static __device__ __forceinline__ int strip_end(int it) {
    return (it < 32) ? (65 * it + (64 - it)) : (65 * (63 - it) + 65);
}

// ============================================================================
// Kernel 1: normalize -> fp16, labels, zero row-slot scratch (2 rows/warp).
// ============================================================================
__global__ void prep_kernel(const float* __restrict__ feats,
                            const float* __restrict__ posf,
                            const int* __restrict__ labels) {
    int wrp  = blockIdx.x * 8 + (threadIdx.x >> 5);
    int lane = threadIdx.x & 31;
    int rowA = wrp * 2;
    int rowB = rowA + 1;

    const float* srcA = (rowA < B_HALF) ? (feats + (size_t)rowA * D_DIM)
                                        : (posf + (size_t)(rowA - B_HALF) * D_DIM);
    const float* srcB = (rowB < B_HALF) ? (feats + (size_t)rowB * D_DIM)
                                        : (posf + (size_t)(rowB - B_HALF) * D_DIM);
    const float4* a4 = reinterpret_cast<const float4*>(srcA);
    const float4* b4 = reinterpret_cast<const float4*>(srcB);
    float4 a0 = a4[lane], a1 = a4[lane + 32];
    float4 b0 = b4[lane], b1 = b4[lane + 32];

    float sa = a0.x*a0.x + a0.y*a0.y + a0.z*a0.z + a0.w*a0.w
             + a1.x*a1.x + a1.y*a1.y + a1.z*a1.z + a1.w*a1.w;
    float sb = b0.x*b0.x + b0.y*b0.y + b0.z*b0.z + b0.w*b0.w
             + b1.x*b1.x + b1.y*b1.y + b1.z*b1.z + b1.w*b1.w;
    #pragma unroll
    for (int off = 16; off > 0; off >>= 1) {
        sa += __shfl_xor_sync(0xffffffffu, sa, off);
        sb += __shfl_xor_sync(0xffffffffu, sb, off);
    }
    float ia = rsqrtf(sa);
    float ib = rsqrtf(sb);

    uint2 oa0, oa1, ob0, ob1;
    oa0.x = pack_h2(a0.x * ia, a0.y * ia);  oa0.y = pack_h2(a0.z * ia, a0.w * ia);
    oa1.x = pack_h2(a1.x * ia, a1.y * ia);  oa1.y = pack_h2(a1.z * ia, a1.w * ia);
    ob0.x = pack_h2(b0.x * ib, b0.y * ib);  ob0.y = pack_h2(b0.z * ib, b0.w * ib);
    ob1.x = pack_h2(b1.x * ib, b1.y * ib);  ob1.y = pack_h2(b1.z * ib, b1.w * ib);

    uint2* dA = reinterpret_cast<uint2*>(g_h + (size_t)rowA * D_DIM);
    uint2* dB = reinterpret_cast<uint2*>(g_h + (size_t)rowB * D_DIM);
    dA[lane] = oa0; dA[lane + 32] = oa1;
    dB[lane] = ob0; dB[lane + 32] = ob1;
    if (lane == 0) {
        lab_buf[rowA] = labels[(rowA < B_HALF) ? rowA : rowA - B_HALF];
        lab_buf[rowB] = labels[(rowB < B_HALF) ? rowB : rowB - B_HALF];
    }

    int gidx = blockIdx.x * blockDim.x + threadIdx.x;
    if (gidx < (16 * N_TOT) / 4)
        reinterpret_cast<float4*>(scratch)[gidx] = make_float4(0.f, 0.f, 0.f, 0.f);
}

static __device__ __forceinline__ void issue_tile(uint32_t sbuf, int row0, int tid) {
    const uint4* src = reinterpret_cast<const uint4*>(g_h);
    #pragma unroll
    for (int t = 0; t < 16; t++) {
        int id = tid + t * 256;
        int r  = id >> 5;
        int kc = id & 31;
        cp16(sbuf + r * ROW_BYTES + kc * 16, src + (size_t)(row0 + r) * 32 + kc);
    }
}

static __device__ __forceinline__ void mma_tile(uint32_t (&acc)[4][4][2],
                                                uint32_t a_lane, uint32_t b_lane) {
    #pragma unroll
    for (int ms = 0; ms < 4; ms++)
        #pragma unroll
        for (int ns = 0; ns < 4; ns++) { acc[ms][ns][0] = 0u; acc[ms][ns][1] = 0u; }

    #pragma unroll 2
    for (int ks = 0; ks < K_STEPS; ks++) {
        const uint32_t koff = (uint32_t)(ks * 32);
        uint32_t a[4][4];
        #pragma unroll
        for (int ms = 0; ms < 4; ms++)
            ldsm_x4(a[ms][0], a[ms][1], a[ms][2], a[ms][3],
                    a_lane + (uint32_t)(ms * 16 * ROW_BYTES) + koff);
        uint32_t b[2][4];
        #pragma unroll
        for (int p = 0; p < 2; p++)
            ldsm_x4(b[p][0], b[p][1], b[p][2], b[p][3],
                    b_lane + (uint32_t)(p * 16 * ROW_BYTES) + koff);
        #pragma unroll
        for (int ms = 0; ms < 4; ms++) {
            mma16816_f16(acc[ms][0], a[ms], b[0][0], b[0][2]);
            mma16816_f16(acc[ms][1], a[ms], b[0][1], b[0][3]);
            mma16816_f16(acc[ms][2], a[ms], b[1][0], b[1][2]);
            mma16816_f16(acc[ms][3], a[ms], b[1][1], b[1][3]);
        }
    }
}

template <bool DIAG>
static __device__ __forceinline__ void epilogue(const uint32_t (&acc)[4][4][2],
        int i0, int it, int jt, int wm, int wn, int lane,
        const int (&labr)[8], float (&sall)[8], float (&spos)[8]) {
    const float K_EXP = 14.42695040888963f;
    const int jbase = jt * TILE_M;
    int labc[4][2];
    #pragma unroll
    for (int ns = 0; ns < 4; ns++) {
        int c0 = jbase + wn * 32 + ns * 8 + (lane & 3) * 2;
        labc[ns][0] = lab_buf[c0];
        labc[ns][1] = lab_buf[c0 + 1];
    }
    float ecall[8], ecpos[8];
    #pragma unroll
    for (int x = 0; x < 8; x++) { ecall[x] = 0.f; ecpos[x] = 0.f; }

    #pragma unroll
    for (int ms = 0; ms < 4; ms++) {
        const int gi_lo = i0 + wm * 64 + ms * 16 + (lane >> 2);
        #pragma unroll
        for (int ns = 0; ns < 4; ns++) {
            const int gj0 = jbase + wn * 32 + ns * 8 + (lane & 3) * 2;
            float2 vlo = __half22float2(*reinterpret_cast<const __half2*>(&acc[ms][ns][0]));
            float2 vhi = __half22float2(*reinterpret_cast<const __half2*>(&acc[ms][ns][1]));
            float vals[4] = { vlo.x, vlo.y, vhi.x, vhi.y };
            #pragma unroll
            for (int c = 0; c < 4; c++) {
                const int rh   = c >> 1;
                const int slot = ms * 2 + rh;
                const int b    = c & 1;
                float e = ex2f(vals[c] * K_EXP);
                bool match = (labc[ns][b] == labr[slot]);
                if (DIAG) {
                    if ((gi_lo + rh * 8) != (gj0 + b)) {
                        sall[slot] += e;
                        if (match) spos[slot] += e;
                    }
                } else {
                    sall[slot] += e;
                    ecall[ns * 2 + b] += e;
                    if (match) { spos[slot] += e; ecpos[ns * 2 + b] += e; }
                }
            }
        }
    }

    if (!DIAG) {
        #pragma unroll
        for (int x = 0; x < 8; x++) {
            #pragma unroll
            for (int off = 4; off < 32; off <<= 1) {
                ecall[x] += __shfl_xor_sync(0xffffffffu, ecall[x], off);
                ecpos[x] += __shfl_xor_sync(0xffffffffu, ecpos[x], off);
            }
        }
        if (lane < 4) {
            const int slot = it * 2 + wm;
            float2* pa = reinterpret_cast<float2*>(scratch + PC_ALL + (size_t)slot * N_TOT);
            float2* pp = reinterpret_cast<float2*>(scratch + PC_POS + (size_t)slot * N_TOT);
            #pragma unroll
            for (int ns = 0; ns < 4; ns++) {
                int cidx = (jbase + wn * 32 + ns * 8 + lane * 2) >> 1;
                pa[cidx] = make_float2(ecall[ns * 2], ecall[ns * 2 + 1]);
                pp[cidx] = make_float2(ecpos[ns * 2], ecpos[ns * 2 + 1]);
            }
        }
    }
}

static __device__ __forceinline__ void flush_rows(char* smem, float (&sall)[8],
        float (&spos)[8], int i0, int rslot, int wm, int wn, int lane, int tid) {
    #pragma unroll
    for (int s = 0; s < 8; s++) {
        sall[s] += __shfl_xor_sync(0xffffffffu, sall[s], 1);
        sall[s] += __shfl_xor_sync(0xffffffffu, sall[s], 2);
        spos[s] += __shfl_xor_sync(0xffffffffu, spos[s], 1);
        spos[s] += __shfl_xor_sync(0xffffffffu, spos[s], 2);
    }
    float* red_all = reinterpret_cast<float*>(smem + RED_OFF);
    float* red_pos = red_all + 128 * 4;
    __syncthreads();
    if ((lane & 3) == 0) {
        #pragma unroll
        for (int s = 0; s < 8; s++) {
            int rloc = wm * 64 + (s >> 1) * 16 + (s & 1) * 8 + (lane >> 2);
            red_all[rloc * 4 + wn] = sall[s];
            red_pos[rloc * 4 + wn] = spos[s];
        }
    }
    __syncthreads();
    if (tid < 128) {
        float a = red_all[tid * 4 + 0] + red_all[tid * 4 + 1]
                + red_all[tid * 4 + 2] + red_all[tid * 4 + 3];
        float p = red_pos[tid * 4 + 0] + red_pos[tid * 4 + 1]
                + red_pos[tid * 4 + 2] + red_pos[tid * 4 + 3];
        scratch[PR_ALL + (size_t)rslot * N_TOT + i0 + tid] = a;
        scratch[PR_POS + (size_t)rslot * N_TOT + i0 + tid] = p;
    }
    #pragma unroll
    for (int s = 0; s < 8; s++) { sall[s] = 0.f; spos[s] = 0.f; }
}

// ============================================================================
// Kernel 2: balanced 148-CTA symmetric HMMA gram (f16 acc) + fused finalize
// behind a grid barrier.
// ============================================================================
__global__ void __launch_bounds__(256, 1) milnce_mma_kernel(float* __restrict__ out) {
    extern __shared__ char smem[];
    __shared__ bool is_last;
    const uint32_t sb = smem_u32(smem);

    const int tid  = threadIdx.x;
    const int wid  = tid >> 5;
    const int lane = tid & 31;
    const int wm   = wid >> 2;
    const int wn   = wid & 3;
    const int c    = blockIdx.x;

    const int t0 = (c < 8) ? c * 15 : 120 + (c - 8) * 14;
    const int t1 = t0 + ((c < 8) ? 15 : 14);

    const int lrow16 = (lane & 7) + ((lane >> 3) & 1) * 8;
    const int lkb    = (lane >> 4) * 16;
    const uint32_t a_lane = sb + A_OFF + (uint32_t)((wm * 64 + lrow16) * ROW_BYTES + lkb);
    const uint32_t b_off  = (uint32_t)((wn * 32 + lrow16) * ROW_BYTES + lkb);

    int it, jt0;
    map_u(t0, it, jt0);
    int i0    = it * TILE_M;
    int rslot = c - chunk_of(strip_start(it));

    issue_tile(sb + A_OFF, i0, tid);
    issue_tile(sb + ((t0 & 1) ? B1_OFF : B0_OFF), map_jt(t0) * TILE_M, tid);
    CP_COMMIT();
    issue_tile(sb + (((t0 + 1) & 1) ? B1_OFF : B0_OFF), map_jt(t0 + 1) * TILE_M, tid);
    CP_COMMIT();

    int labr[8];
    #pragma unroll
    for (int s = 0; s < 8; s++)
        labr[s] = lab_buf[i0 + wm * 64 + (s >> 1) * 16 + (s & 1) * 8 + (lane >> 2)];

    float sall[8] = {0,0,0,0,0,0,0,0};
    float spos[8] = {0,0,0,0,0,0,0,0};
    uint32_t accA[4][4][2], accB[4][4][2];

    auto b_lane_of = [&](int x) -> uint32_t {
        return sb + ((x & 1) ? B1_OFF : B0_OFF) + b_off;
    };
    auto wait_for = [&](int x) {
        if (x + 1 < t1) { CP_WAIT(1); } else { CP_WAIT(0); }
        __syncthreads();
    };
    auto post_mma = [&](int x) {
        __syncthreads();
        if (x + 2 < t1) {
            issue_tile(sb + ((x & 1) ? B1_OFF : B0_OFF), map_jt(x + 2) * TILE_M, tid);
            CP_COMMIT();
        }
    };
    auto do_epi = [&](const uint32_t (&acc)[4][4][2], int x) {
        int jtv = map_jt(x);
        if (jtv == it) epilogue<true >(acc, i0, it, jtv, wm, wn, lane, labr, sall, spos);
        else           epilogue<false>(acc, i0, it, jtv, wm, wn, lane, labr, sall, spos);
    };

    int u = t0;
    #pragma unroll 1
    while (u < t1) {
        const int s1 = min(t1, strip_end(it));

        wait_for(u);
        mma_tile(accA, a_lane, b_lane_of(u));
        post_mma(u);

        int v = u + 1;
        #pragma unroll 1
        for (; v + 1 < s1; v += 2) {
            wait_for(v);
            mma_tile(accB, a_lane, b_lane_of(v));
            post_mma(v);
            do_epi(accA, v - 1);

            wait_for(v + 1);
            mma_tile(accA, a_lane, b_lane_of(v + 1));
            post_mma(v + 1);
            do_epi(accB, v);
        }
        if (v < s1) {
            wait_for(v);
            mma_tile(accB, a_lane, b_lane_of(v));
            post_mma(v);
            do_epi(accA, v - 1);
            do_epi(accB, v);
        } else {
            do_epi(accA, s1 - 1);
        }

        flush_rows(smem, sall, spos, i0, rslot, wm, wn, lane, tid);

        u = s1;
        if (u < t1) {
            int njt;
            map_u(u, it, njt);
            i0    = it * TILE_M;
            rslot = c - chunk_of(strip_start(it));
            #pragma unroll
            for (int s = 0; s < 8; s++)
                labr[s] = lab_buf[i0 + wm * 64 + (s >> 1) * 16 + (s & 1) * 8 + (lane >> 2)];
            CP_WAIT(0);
            __syncthreads();
            issue_tile(sb + A_OFF, i0, tid);
            CP_COMMIT();
            CP_WAIT(0);
            __syncthreads();
        }
    }

    // ---------------- Phase 2: fused finalize (after grid barrier) ----------
    grid_bar(&g_cnt2, &g_flag2);

    float warp_part = 0.f;
    #pragma unroll 1
    for (int k = 0; k < ROWS_PER_CTA / 8; k++) {
        int row = c * ROWS_PER_CTA + wid * (ROWS_PER_CTA / 8) + k;  // uniform per warp
        if (row < N_TOT) {
            int jt = row >> 7;
            float a = 0.f, p = 0.f;
            if (lane < 8) {
                a += scratch[PR_ALL + (size_t)lane * N_TOT + row];
                p += scratch[PR_POS + (size_t)lane * N_TOT + row];
            }
            for (int s = lane; s < 2 * jt; s += 32) {
                a += scratch[PC_ALL + (size_t)s * N_TOT + row];
                p += scratch[PC_POS + (size_t)s * N_TOT + row];
            }
            #pragma unroll
            for (int off = 16; off > 0; off >>= 1) {
                a += __shfl_xor_sync(0xffffffffu, a, off);
                p += __shfl_xor_sync(0xffffffffu, p, off);
            }
            if (lane == 0) warp_part += logf(a) - logf(p);
        }
    }
    float* wred = reinterpret_cast<float*>(smem + RED_OFF);
    __syncthreads();
    if (lane == 0) wred[wid] = warp_part;
    __syncthreads();
    if (tid == 0) {
        float bsum = 0.f;
        #pragma unroll
        for (int w = 0; w < 8; w++) bsum += wred[w];
        blocksum[c] = bsum;
        __threadfence();
        unsigned t = atomicInc(&g_cnt3, NCTA - 1);
        is_last = (t == NCTA - 1);
    }
    __syncthreads();
    if (is_last) {
        float* red = reinterpret_cast<float*>(smem + RED_OFF);
        red[tid] = (tid < NCTA) ? blocksum[tid] : 0.f;
        __syncthreads();
        #pragma unroll
        for (int o = 128; o > 0; o >>= 1) {
            if (tid < o) red[tid] += red[tid + o];
            __syncthreads();
        }
        if (tid == 0) {
            out[0] = red[0];
            g_flag2 = 0;           // reset for graph replay
            __threadfence();
        }
    }
}

// ============================================================================
extern "C" void kernel_launch(void* const* d_in, const int* in_sizes, int n_in,
                              void* d_out, int out_size) {
    const float* feats  = (const float*)d_in[0];
    const float* posf   = (const float*)d_in[1];
    const int*   labels = (const int*)d_in[2];

    prep_kernel<<<512, 256>>>(feats, posf, labels);

    cudaFuncSetAttribute(milnce_mma_kernel,
                         cudaFuncAttributeMaxDynamicSharedMemorySize, SMEM_TOTAL);
    milnce_mma_kernel<<<NCTA, 256, SMEM_TOTAL>>>((float*)d_out);
}

// round 15
// speedup vs baseline: 1.1441x; 1.1441x over previous
#include <cuda_runtime.h>
#include <cuda_fp16.h>
#include <cstdint>

#define N_TOT   8192
#define D_DIM   256
#define TILE_M  128
#define B_HALF  4096
#define NROWT   64
#define K_STEPS 16
#define NTILES  2080
#define NCTA    148

#define ROW_BYTES 528
#define A_OFF   0
#define B0_OFF  (TILE_M * ROW_BYTES)
#define B1_OFF  (B0_OFF + TILE_M * ROW_BYTES)
#define RED_OFF (B1_OFF + TILE_M * ROW_BYTES)
#define SMEM_TOTAL (RED_OFF + 128 * 4 * 2 * 4)

// -------- device scratch --------
__device__ __align__(16) __half g_h[N_TOT * D_DIM];
__device__ int   lab_buf[N_TOT];

// PR slots: BSS zero-init; every written (slot,row) pair is rewritten
// deterministically each launch (static schedule), unwritten pairs stay 0.
// -> no per-launch zeroing needed. PC slots [0,2*jt) per column tile are
// always written before finalize reads them.
#define PR_ALL  0
#define PR_POS  (8 * N_TOT)
#define PC_ALL  (16 * N_TOT)
#define PC_POS  (PC_ALL + 128 * N_TOT)
#define SCRATCH_FLOATS (PC_POS + 128 * N_TOT)
__device__ __align__(16) float scratch[SCRATCH_FLOATS];
__device__ float blocksum[64];
__device__ unsigned int fin_counter = 0;

// ======================= helpers =======================
static __device__ __forceinline__ uint32_t smem_u32(const void* p) {
    uint32_t a;
    asm("{ .reg .u64 t; cvta.to.shared.u64 t, %1; cvt.u32.u64 %0, t; }" : "=r"(a) : "l"(p));
    return a;
}
static __device__ __forceinline__ float ex2f(float x) {
    float r; asm("ex2.approx.ftz.f32 %0, %1;" : "=f"(r) : "f"(x)); return r;
}
static __device__ __forceinline__ uint32_t pack_h2(float lo, float hi) {
    uint32_t r; asm("cvt.rn.f16x2.f32 %0, %1, %2;" : "=r"(r) : "f"(hi), "f"(lo)); return r;
}
static __device__ __forceinline__ void cp16(uint32_t saddr, const void* g) {
    asm volatile("cp.async.cg.shared.global [%0], [%1], 16;" :: "r"(saddr), "l"(g) : "memory");
}
#define CP_COMMIT() asm volatile("cp.async.commit_group;" ::: "memory")
#define CP_WAIT(n)  asm volatile("cp.async.wait_group %0;" :: "n"(n) : "memory")

static __device__ __forceinline__ void ldsm_x4(uint32_t& r0, uint32_t& r1,
                                               uint32_t& r2, uint32_t& r3, uint32_t a) {
    asm volatile("ldmatrix.sync.aligned.m8n8.x4.shared.b16 {%0,%1,%2,%3}, [%4];"
                 : "=r"(r0), "=r"(r1), "=r"(r2), "=r"(r3) : "r"(a));
}
// f16-accumulate MMA (confirmed fastest available tensor path on this toolchain)
static __device__ __forceinline__ void mma16816_f16(uint32_t* d, const uint32_t* a,
                                                    uint32_t b0, uint32_t b1) {
    asm volatile(
        "mma.sync.aligned.m16n8k16.row.col.f16.f16.f16.f16 "
        "{%0,%1}, {%2,%3,%4,%5}, {%6,%7}, {%0,%1};"
        : "+r"(d[0]), "+r"(d[1])
        : "r"(a[0]), "r"(a[1]), "r"(a[2]), "r"(a[3]), "r"(b0), "r"(b1));
}

// ---- schedule mapping (pair order: [64][1][63][2]...[33][32]) ----
static __device__ __forceinline__ void map_u(int u, int& it, int& jt) {
    int p = u / 65, off = u - p * 65;
    int l0 = 64 - p;
    if (off < l0) { it = p;      jt = p + off; }
    else          { it = 63 - p; jt = (63 - p) + (off - l0); }
}
static __device__ __forceinline__ int map_jt(int u) {
    int it, jt; map_u(u, it, jt); return jt;
}
static __device__ __forceinline__ int chunk_of(int u) {
    return (u < 120) ? (u / 15) : (8 + (u - 120) / 14);
}
static __device__ __forceinline__ int strip_start(int it) {
    int p = (it < 32) ? it : 63 - it;
    return (it < 32) ? (65 * p) : (65 * p + (64 - p));
}
static __device__ __forceinline__ int strip_end(int it) {
    return (it < 32) ? (65 * it + (64 - it)) : (65 * (63 - it) + 65);
}

// ============================================================================
// Kernel 1: normalize -> fp16, labels. 2 independent rows per warp.
// ============================================================================
__global__ void prep_kernel(const float* __restrict__ feats,
                            const float* __restrict__ posf,
                            const int* __restrict__ labels) {
    int wrp  = blockIdx.x * 8 + (threadIdx.x >> 5);   // 0..4095
    int lane = threadIdx.x & 31;
    int rowA = wrp * 2;
    int rowB = rowA + 1;

    const float* srcA = (rowA < B_HALF) ? (feats + (size_t)rowA * D_DIM)
                                        : (posf + (size_t)(rowA - B_HALF) * D_DIM);
    const float* srcB = (rowB < B_HALF) ? (feats + (size_t)rowB * D_DIM)
                                        : (posf + (size_t)(rowB - B_HALF) * D_DIM);
    const float4* a4 = reinterpret_cast<const float4*>(srcA);
    const float4* b4 = reinterpret_cast<const float4*>(srcB);
    float4 a0 = a4[lane], a1 = a4[lane + 32];
    float4 b0 = b4[lane], b1 = b4[lane + 32];

    float sa = a0.x*a0.x + a0.y*a0.y + a0.z*a0.z + a0.w*a0.w
             + a1.x*a1.x + a1.y*a1.y + a1.z*a1.z + a1.w*a1.w;
    float sb = b0.x*b0.x + b0.y*b0.y + b0.z*b0.z + b0.w*b0.w
             + b1.x*b1.x + b1.y*b1.y + b1.z*b1.z + b1.w*b1.w;
    #pragma unroll
    for (int off = 16; off > 0; off >>= 1) {
        sa += __shfl_xor_sync(0xffffffffu, sa, off);
        sb += __shfl_xor_sync(0xffffffffu, sb, off);
    }
    float ia = rsqrtf(sa);
    float ib = rsqrtf(sb);

    uint2 oa0, oa1, ob0, ob1;
    oa0.x = pack_h2(a0.x * ia, a0.y * ia);  oa0.y = pack_h2(a0.z * ia, a0.w * ia);
    oa1.x = pack_h2(a1.x * ia, a1.y * ia);  oa1.y = pack_h2(a1.z * ia, a1.w * ia);
    ob0.x = pack_h2(b0.x * ib, b0.y * ib);  ob0.y = pack_h2(b0.z * ib, b0.w * ib);
    ob1.x = pack_h2(b1.x * ib, b1.y * ib);  ob1.y = pack_h2(b1.z * ib, b1.w * ib);

    uint2* dA = reinterpret_cast<uint2*>(g_h + (size_t)rowA * D_DIM);
    uint2* dB = reinterpret_cast<uint2*>(g_h + (size_t)rowB * D_DIM);
    dA[lane] = oa0; dA[lane + 32] = oa1;
    dB[lane] = ob0; dB[lane + 32] = ob1;
    if (lane == 0) {
        lab_buf[rowA] = labels[(rowA < B_HALF) ? rowA : rowA - B_HALF];
        lab_buf[rowB] = labels[(rowB < B_HALF) ? rowB : rowB - B_HALF];
    }
}

static __device__ __forceinline__ void issue_tile(uint32_t sbuf, int row0, int tid) {
    const uint4* src = reinterpret_cast<const uint4*>(g_h);
    #pragma unroll
    for (int t = 0; t < 16; t++) {
        int id = tid + t * 256;
        int r  = id >> 5;
        int kc = id & 31;
        cp16(sbuf + r * ROW_BYTES + kc * 16, src + (size_t)(row0 + r) * 32 + kc);
    }
}

static __device__ __forceinline__ void mma_tile(uint32_t (&acc)[4][4][2],
                                                uint32_t a_lane, uint32_t b_lane) {
    #pragma unroll
    for (int ms = 0; ms < 4; ms++)
        #pragma unroll
        for (int ns = 0; ns < 4; ns++) { acc[ms][ns][0] = 0u; acc[ms][ns][1] = 0u; }

    #pragma unroll 2
    for (int ks = 0; ks < K_STEPS; ks++) {
        const uint32_t koff = (uint32_t)(ks * 32);
        uint32_t a[4][4];
        #pragma unroll
        for (int ms = 0; ms < 4; ms++)
            ldsm_x4(a[ms][0], a[ms][1], a[ms][2], a[ms][3],
                    a_lane + (uint32_t)(ms * 16 * ROW_BYTES) + koff);
        uint32_t b[2][4];
        #pragma unroll
        for (int p = 0; p < 2; p++)
            ldsm_x4(b[p][0], b[p][1], b[p][2], b[p][3],
                    b_lane + (uint32_t)(p * 16 * ROW_BYTES) + koff);
        #pragma unroll
        for (int ms = 0; ms < 4; ms++) {
            mma16816_f16(acc[ms][0], a[ms], b[0][0], b[0][2]);
            mma16816_f16(acc[ms][1], a[ms], b[0][1], b[0][3]);
            mma16816_f16(acc[ms][2], a[ms], b[1][0], b[1][2]);
            mma16816_f16(acc[ms][3], a[ms], b[1][1], b[1][3]);
        }
    }
}

template <bool DIAG>
static __device__ __forceinline__ void epilogue(const uint32_t (&acc)[4][4][2],
        int i0, int it, int jt, int wm, int wn, int lane,
        const int (&labr)[8], float (&sall)[8], float (&spos)[8]) {
    const float K_EXP = 14.42695040888963f;
    const int jbase = jt * TILE_M;
    int labc[4][2];
    #pragma unroll
    for (int ns = 0; ns < 4; ns++) {
        int c0 = jbase + wn * 32 + ns * 8 + (lane & 3) * 2;
        labc[ns][0] = lab_buf[c0];
        labc[ns][1] = lab_buf[c0 + 1];
    }
    float ecall[8], ecpos[8];
    #pragma unroll
    for (int x = 0; x < 8; x++) { ecall[x] = 0.f; ecpos[x] = 0.f; }

    #pragma unroll
    for (int ms = 0; ms < 4; ms++) {
        const int gi_lo = i0 + wm * 64 + ms * 16 + (lane >> 2);
        #pragma unroll
        for (int ns = 0; ns < 4; ns++) {
            const int gj0 = jbase + wn * 32 + ns * 8 + (lane & 3) * 2;
            float2 vlo = __half22float2(*reinterpret_cast<const __half2*>(&acc[ms][ns][0]));
            float2 vhi = __half22float2(*reinterpret_cast<const __half2*>(&acc[ms][ns][1]));
            float vals[4] = { vlo.x, vlo.y, vhi.x, vhi.y };
            #pragma unroll
            for (int c = 0; c < 4; c++) {
                const int rh   = c >> 1;
                const int slot = ms * 2 + rh;
                const int b    = c & 1;
                float e = ex2f(vals[c] * K_EXP);
                bool match = (labc[ns][b] == labr[slot]);
                if (DIAG) {
                    if ((gi_lo + rh * 8) != (gj0 + b)) {
                        sall[slot] += e;
                        if (match) spos[slot] += e;
                    }
                } else {
                    sall[slot] += e;
                    ecall[ns * 2 + b] += e;
                    if (match) { spos[slot] += e; ecpos[ns * 2 + b] += e; }
                }
            }
        }
    }

    if (!DIAG) {
        #pragma unroll
        for (int x = 0; x < 8; x++) {
            #pragma unroll
            for (int off = 4; off < 32; off <<= 1) {
                ecall[x] += __shfl_xor_sync(0xffffffffu, ecall[x], off);
                ecpos[x] += __shfl_xor_sync(0xffffffffu, ecpos[x], off);
            }
        }
        if (lane < 4) {
            const int slot = it * 2 + wm;
            float2* pa = reinterpret_cast<float2*>(scratch + PC_ALL + (size_t)slot * N_TOT);
            float2* pp = reinterpret_cast<float2*>(scratch + PC_POS + (size_t)slot * N_TOT);
            #pragma unroll
            for (int ns = 0; ns < 4; ns++) {
                int cidx = (jbase + wn * 32 + ns * 8 + lane * 2) >> 1;
                pa[cidx] = make_float2(ecall[ns * 2], ecall[ns * 2 + 1]);
                pp[cidx] = make_float2(ecpos[ns * 2], ecpos[ns * 2 + 1]);
            }
        }
    }
}

static __device__ __forceinline__ void flush_rows(char* smem, float (&sall)[8],
        float (&spos)[8], int i0, int rslot, int wm, int wn, int lane, int tid) {
    #pragma unroll
    for (int s = 0; s < 8; s++) {
        sall[s] += __shfl_xor_sync(0xffffffffu, sall[s], 1);
        sall[s] += __shfl_xor_sync(0xffffffffu, sall[s], 2);
        spos[s] += __shfl_xor_sync(0xffffffffu, spos[s], 1);
        spos[s] += __shfl_xor_sync(0xffffffffu, spos[s], 2);
    }
    float* red_all = reinterpret_cast<float*>(smem + RED_OFF);
    float* red_pos = red_all + 128 * 4;
    __syncthreads();
    if ((lane & 3) == 0) {
        #pragma unroll
        for (int s = 0; s < 8; s++) {
            int rloc = wm * 64 + (s >> 1) * 16 + (s & 1) * 8 + (lane >> 2);
            red_all[rloc * 4 + wn] = sall[s];
            red_pos[rloc * 4 + wn] = spos[s];
        }
    }
    __syncthreads();
    if (tid < 128) {
        float a = red_all[tid * 4 + 0] + red_all[tid * 4 + 1]
                + red_all[tid * 4 + 2] + red_all[tid * 4 + 3];
        float p = red_pos[tid * 4 + 0] + red_pos[tid * 4 + 1]
                + red_pos[tid * 4 + 2] + red_pos[tid * 4 + 3];
        scratch[PR_ALL + (size_t)rslot * N_TOT + i0 + tid] = a;
        scratch[PR_POS + (size_t)rslot * N_TOT + i0 + tid] = p;
    }
    #pragma unroll
    for (int s = 0; s < 8; s++) { sall[s] = 0.f; spos[s] = 0.f; }
}

// ============================================================================
// Kernel 2: balanced 148-CTA symmetric HMMA gram (f16 accumulate).
// ============================================================================
__global__ void __launch_bounds__(256, 1) milnce_mma_kernel() {
    extern __shared__ char smem[];
    const uint32_t sb = smem_u32(smem);

    const int tid  = threadIdx.x;
    const int wid  = tid >> 5;
    const int lane = tid & 31;
    const int wm   = wid >> 2;
    const int wn   = wid & 3;
    const int c    = blockIdx.x;

    const int t0 = (c < 8) ? c * 15 : 120 + (c - 8) * 14;
    const int t1 = t0 + ((c < 8) ? 15 : 14);

    const int lrow16 = (lane & 7) + ((lane >> 3) & 1) * 8;
    const int lkb    = (lane >> 4) * 16;
    const uint32_t a_lane = sb + A_OFF + (uint32_t)((wm * 64 + lrow16) * ROW_BYTES + lkb);
    const uint32_t b_off  = (uint32_t)((wn * 32 + lrow16) * ROW_BYTES + lkb);

    int it, jt0;
    map_u(t0, it, jt0);
    int i0    = it * TILE_M;
    int rslot = c - chunk_of(strip_start(it));

    issue_tile(sb + A_OFF, i0, tid);
    issue_tile(sb + ((t0 & 1) ? B1_OFF : B0_OFF), map_jt(t0) * TILE_M, tid);
    CP_COMMIT();
    issue_tile(sb + (((t0 + 1) & 1) ? B1_OFF : B0_OFF), map_jt(t0 + 1) * TILE_M, tid);
    CP_COMMIT();

    int labr[8];
    #pragma unroll
    for (int s = 0; s < 8; s++)
        labr[s] = lab_buf[i0 + wm * 64 + (s >> 1) * 16 + (s & 1) * 8 + (lane >> 2)];

    float sall[8] = {0,0,0,0,0,0,0,0};
    float spos[8] = {0,0,0,0,0,0,0,0};
    uint32_t accA[4][4][2], accB[4][4][2];

    auto b_lane_of = [&](int x) -> uint32_t {
        return sb + ((x & 1) ? B1_OFF : B0_OFF) + b_off;
    };
    auto wait_for = [&](int x) {
        if (x + 1 < t1) { CP_WAIT(1); } else { CP_WAIT(0); }
        __syncthreads();
    };
    auto post_mma = [&](int x) {
        __syncthreads();
        if (x + 2 < t1) {
            issue_tile(sb + ((x & 1) ? B1_OFF : B0_OFF), map_jt(x + 2) * TILE_M, tid);
            CP_COMMIT();
        }
    };
    auto do_epi = [&](const uint32_t (&acc)[4][4][2], int x) {
        int jtv = map_jt(x);
        if (jtv == it) epilogue<true >(acc, i0, it, jtv, wm, wn, lane, labr, sall, spos);
        else           epilogue<false>(acc, i0, it, jtv, wm, wn, lane, labr, sall, spos);
    };

    int u = t0;
    #pragma unroll 1
    while (u < t1) {
        const int s1 = min(t1, strip_end(it));

        wait_for(u);
        mma_tile(accA, a_lane, b_lane_of(u));
        post_mma(u);

        int v = u + 1;
        #pragma unroll 1
        for (; v + 1 < s1; v += 2) {
            wait_for(v);
            mma_tile(accB, a_lane, b_lane_of(v));
            post_mma(v);
            do_epi(accA, v - 1);

            wait_for(v + 1);
            mma_tile(accA, a_lane, b_lane_of(v + 1));
            post_mma(v + 1);
            do_epi(accB, v);
        }
        if (v < s1) {
            wait_for(v);
            mma_tile(accB, a_lane, b_lane_of(v));
            post_mma(v);
            do_epi(accA, v - 1);
            do_epi(accB, v);
        } else {
            do_epi(accA, s1 - 1);
        }

        flush_rows(smem, sall, spos, i0, rslot, wm, wn, lane, tid);

        u = s1;
        if (u < t1) {
            int njt;
            map_u(u, it, njt);
            i0    = it * TILE_M;
            rslot = c - chunk_of(strip_start(it));
            #pragma unroll
            for (int s = 0; s < 8; s++)
                labr[s] = lab_buf[i0 + wm * 64 + (s >> 1) * 16 + (s & 1) * 8 + (lane >> 2)];
            CP_WAIT(0);
            __syncthreads();
            issue_tile(sb + A_OFF, i0, tid);
            CP_COMMIT();
            CP_WAIT(0);
            __syncthreads();
        }
    }
}

// ============================================================================
// Kernel 3: per-row loss (2 threads per row: even/odd slots) + last-block total.
// ============================================================================
__global__ void finalize_kernel(float* __restrict__ out) {
    __shared__ float red[128];
    __shared__ float half_a[256], half_p[256];
    __shared__ bool  is_last;
    const int blk  = blockIdx.x;
    const int tid  = threadIdx.x;
    const int r    = tid & 127;
    const int par  = tid >> 7;
    const int i    = blk * 128 + r;
    const int jt   = blk;

    float a = 0.f, p = 0.f;
    #pragma unroll
    for (int s = par * 4; s < par * 4 + 4; s++) {
        a += scratch[PR_ALL + (size_t)s * N_TOT + i];
        p += scratch[PR_POS + (size_t)s * N_TOT + i];
    }
    const int nslots = 2 * jt;
    #pragma unroll 4
    for (int s = par; s < nslots; s += 2) {
        a += scratch[PC_ALL + (size_t)s * N_TOT + i];
        p += scratch[PC_POS + (size_t)s * N_TOT + i];
    }
    half_a[tid] = a;
    half_p[tid] = p;
    __syncthreads();
    if (tid < 128) {
        float ta = half_a[tid] + half_a[tid + 128];
        float tp = half_p[tid] + half_p[tid + 128];
        red[tid] = logf(ta) - logf(tp);
    }
    __syncthreads();
    #pragma unroll
    for (int o = 64; o > 0; o >>= 1) {
        if (tid < o) red[tid] += red[tid + o];
        __syncthreads();
    }
    if (tid == 0) {
        blocksum[blk] = red[0];
        __threadfence();
        unsigned int t = atomicInc(&fin_counter, 63);
        is_last = (t == 63);
    }
    __syncthreads();
    if (is_last) {
        float s = (tid < 64) ? blocksum[tid] : 0.f;
        if (tid < 128) red[tid] = (tid < 64) ? s : 0.f;
        __syncthreads();
        #pragma unroll
        for (int o = 64; o > 0; o >>= 1) {
            if (tid < o) red[tid] += red[tid + o];
            __syncthreads();
        }
        if (tid == 0) out[0] = red[0];
    }
}

// ============================================================================
extern "C" void kernel_launch(void* const* d_in, const int* in_sizes, int n_in,
                              void* d_out, int out_size) {
    const float* feats  = (const float*)d_in[0];
    const float* posf   = (const float*)d_in[1];
    const int*   labels = (const int*)d_in[2];

    prep_kernel<<<512, 256>>>(feats, posf, labels);

    cudaFuncSetAttribute(milnce_mma_kernel,
                         cudaFuncAttributeMaxDynamicSharedMemorySize, SMEM_TOTAL);
    milnce_mma_kernel<<<NCTA, 256, SMEM_TOTAL>>>();

    finalize_kernel<<<64, 256>>>((float*)d_out);
}